// round 17
// baseline (speedup 1.0000x reference)
#include <cuda_runtime.h>
#include <cuda_fp16.h>
#include <math.h>
#include <stdint.h>

// Problem constants
#define PB   16      // batch
#define PC   256     // channels
#define PN   4096    // H*W
#define PNH  4       // heads
#define PHD  32      // head dim
#define PNM  4       // memory tokens
#define PHID 128     // NH*HD
#define QROWS 384    // 3*HID

typedef unsigned long long u64;
typedef unsigned int u32;

// ---------------- scratch (static device memory; no allocation) ----------------
__device__ unsigned short g_wh[QROWS * PC];            // fp16 hi of scaled qkv weights
__device__ unsigned short g_wl[QROWS * PC];            // fp16 lo
__device__ unsigned short g_xh[(size_t)PB * PN * PC];  // fp16 of normalized x, [b][n][c]
__device__ float g_q[(size_t)PB * PHID * PN];          // q activations f32 (~33 MB)
__device__ unsigned short g_kv16[(size_t)PB * 256 * PN]; // k rows 0-127, v rows 128-255, fp16 (~33 MB)
__device__ float g_stat[2][PB * PNH * PHD];            // k softmax: rowmax, 1/rowsum
__device__ float g_ctxp[8][PB * PNH * PHD * PHD];      // partial contexts (8 token chunks)
__device__ unsigned short g_Mh[PB * PC * PHID];        // folded M = w_out . ctx, fp16 hi
__device__ unsigned short g_Ml[PB * PC * PHID];        // fp16 lo

// ---------------- small helpers ----------------
__device__ __forceinline__ u32 f16_rn(float v) {
    return (u32)__half_as_ushort(__float2half_rn(v));
}
__device__ __forceinline__ float f16_tof(u32 b) {
    return __half2float(__ushort_as_half((unsigned short)b));
}

__device__ __forceinline__ u32 smem_u32(const void* p) {
    u32 a;
    asm("{ .reg .u64 t; cvta.to.shared.u64 t, %1; cvt.u32.u64 %0, t; }" : "=r"(a) : "l"(p));
    return a;
}

// f32x2 packed helpers (k_context)
__device__ __forceinline__ u64 fma2(u64 a, u64 b, u64 c) {
    u64 d; asm("fma.rn.f32x2 %0, %1, %2, %3;" : "=l"(d) : "l"(a), "l"(b), "l"(c)); return d;
}
__device__ __forceinline__ u64 pack2(float lo, float hi) {
    u64 r; asm("mov.b64 %0, {%1, %2};" : "=l"(r) : "f"(lo), "f"(hi)); return r;
}
__device__ __forceinline__ float2 unpack2(u64 v) {
    float2 r; asm("mov.b64 {%0, %1}, %2;" : "=f"(r.x), "=f"(r.y) : "l"(v)); return r;
}

// ---------------- HMMA helpers ----------------
__device__ __forceinline__ void ldsm4(u32* r, u32 addr) {
    asm volatile("ldmatrix.sync.aligned.m8n8.x4.shared.b16 {%0,%1,%2,%3}, [%4];"
                 : "=r"(r[0]), "=r"(r[1]), "=r"(r[2]), "=r"(r[3]) : "r"(addr));
}
__device__ __forceinline__ void mma16816(float* d, const u32* a, const u32* b) {
    asm volatile(
        "mma.sync.aligned.m16n8k16.row.col.f32.f16.f16.f32 "
        "{%0,%1,%2,%3}, {%4,%5,%6,%7}, {%8,%9}, {%0,%1,%2,%3};"
        : "+f"(d[0]), "+f"(d[1]), "+f"(d[2]), "+f"(d[3])
        : "r"(a[0]), "r"(a[1]), "r"(a[2]), "r"(a[3]), "r"(b[0]), "r"(b[1]));
}
__device__ __forceinline__ void cpa16(u32 dst, const void* src) {
    asm volatile("cp.async.ca.shared.global [%0], [%1], 16;" :: "r"(dst), "l"(src));
}
__device__ __forceinline__ void cpa_commit() {
    asm volatile("cp.async.commit_group;" ::: "memory");
}
__device__ __forceinline__ void cpa_wait1() {
    asm volatile("cp.async.wait_group 1;" ::: "memory");
}
__device__ __forceinline__ void cpa_wait0() {
    asm volatile("cp.async.wait_group 0;" ::: "memory");
}

// ---------------- K0a: weight convert  fp16 hi/lo of (w_qkv * g_in * sqrt(C)) ----------------
__global__ void k_convw(const float* __restrict__ w_qkv, const float* __restrict__ g_in) {
    int i = blockIdx.x * 256 + threadIdx.x;
    if (i < QROWS * PC) {
        int c = i & 255;
        float v = w_qkv[i] * g_in[c] * 16.0f;  // sqrt(256) = 16
        u32 hb = f16_rn(v);
        u32 lb = f16_rn(v - f16_tof(hb));
        g_wh[i] = (unsigned short)hb;
        g_wl[i] = (unsigned short)lb;
    }
}

// ---------------- K0b: fused channel-RMS + transpose + fp16 convert ----------------
#define NORMX_SMEM 68864
__global__ void __launch_bounds__(256) k_normx(const float* __restrict__ x) {
    extern __shared__ char dsm[];
    float* xs = reinterpret_cast<float*>(dsm);            // [c][p], pitch 66
    float* ss = reinterpret_cast<float*>(dsm + 67584);    // [4][64]
    float* inv = reinterpret_cast<float*>(dsm + 68608);   // [64]
    int n0 = blockIdx.x * 64, b = blockIdx.y;
    int tid = threadIdx.x;

#pragma unroll
    for (int i = 0; i < 16; i++) {
        int f4 = tid + i * 256;
        int c = f4 >> 4, p4 = (f4 & 15) << 2;
        float4 v = *reinterpret_cast<const float4*>(
            &x[((size_t)b * PC + c) * PN + n0 + p4]);
        float* row = &xs[c * 66 + p4];
        row[0] = v.x; row[1] = v.y; row[2] = v.z; row[3] = v.w;
    }
    __syncthreads();

    {
        int p = tid & 63, q = tid >> 6;
        float s = 0.0f;
#pragma unroll 8
        for (int c2 = 0; c2 < 64; c2++) {
            float v = xs[(q * 64 + c2) * 66 + p];
            s += v * v;
        }
        ss[q * 64 + p] = s;
    }
    __syncthreads();
    if (tid < 64) {
        float s = ss[tid] + ss[64 + tid] + ss[128 + tid] + ss[192 + tid];
        inv[tid] = 1.0f / fmaxf(sqrtf(s), 1e-12f);
    }
    __syncthreads();

#pragma unroll
    for (int i = 0; i < 32; i++) {
        int e2 = tid + i * 256;
        int n_ = e2 >> 7, cp = (e2 & 127) << 1;
        float iv = inv[n_];
        float v0 = xs[cp * 66 + n_] * iv;
        float v1 = xs[(cp + 1) * 66 + n_] * iv;
        u32 h0 = f16_rn(v0), h1 = f16_rn(v1);
        size_t e = ((size_t)b * PN + n0 + n_) * PC + cp;
        reinterpret_cast<u32*>(g_xh)[e >> 1] = (h1 << 16) | h0;
    }
}

// ---------------- K2: qkv GEMM on HMMA ----------------
// mb_base selects the launch slice: mb = mb_base + blockIdx.y*128.
// q block (mb==0): 2-term (Wh+Wl)*Xh, f32 output.
// k/v blocks (mb=128/256): 1-term Wh*Xh (lo below fp16 output quantization).
#define QKV_SMEM 98304
__global__ void __launch_bounds__(256, 2) k_qkv_mma(int mb_base) {
    extern __shared__ char dyn[];
    u32 base = smem_u32(dyn);
    int tid = threadIdx.x, lane = tid & 31, wid = tid >> 5;
    int nb = blockIdx.x * 128, mb = mb_base + blockIdx.y * 128, b = blockIdx.z;
    int wm = (wid & 3) * 32, wn = (wid >> 2) * 64;
    const bool need_lo = (mb == 0);

    float acc[2][8][4];
#pragma unroll
    for (int im = 0; im < 2; im++)
#pragma unroll
        for (int jn = 0; jn < 8; jn++)
#pragma unroll
            for (int q = 0; q < 4; q++) acc[im][jn][q] = 0.0f;

    u32 st_bo[4];
    const unsigned short* st_wsrc[4];
    const unsigned short* st_xsrc[4];
    bool st_xok[4];
#pragma unroll
    for (int i = 0; i < 4; i++) {
        int u = tid + i * 256;
        int r = u >> 3, c8 = (u & 7) << 3;
        u32 bo = (u32)((r << 7) + (c8 << 1));
        st_bo[i] = bo ^ ((bo >> 3) & 0x70);
        if (c8 < 32) {
            st_wsrc[i] = &g_wh[(size_t)(mb + r) * PC + c8];
            st_xsrc[i] = &g_xh[((size_t)b * PN + nb + r) * PC + c8];
            st_xok[i] = true;
        } else {
            st_wsrc[i] = &g_wl[(size_t)(mb + r) * PC + c8 - 32];
            st_xsrc[i] = 0;
            st_xok[i] = false;
        }
    }
    u32 a_off[2], b_off[4];
#pragma unroll
    for (int im = 0; im < 2; im++) {
        int arow = wm + im * 16 + (lane & 15);
        u32 bo = (u32)(arow * 128) + ((lane >> 4) << 4);
        a_off[im] = bo ^ ((bo >> 3) & 0x70);
    }
#pragma unroll
    for (int j2 = 0; j2 < 4; j2++) {
        int nrow = wn + j2 * 16 + ((lane >> 4) << 3) + (lane & 7);
        u32 bo = (u32)(nrow * 128) + (((lane >> 3) & 1) << 4);
        b_off[j2] = bo ^ ((bo >> 3) & 0x70);
    }

#pragma unroll
    for (int s = 0; s < 2; s++) {
        u32 sb = base + (u32)(s * 32768);
        int co = s * 32;
#pragma unroll
        for (int i = 0; i < 4; i++) {
            if (st_xok[i]) {
                cpa16(sb + st_bo[i], st_wsrc[i] + co);
                cpa16(sb + 16384 + st_bo[i], st_xsrc[i] + co);
            } else if (need_lo) {
                cpa16(sb + st_bo[i], st_wsrc[i] + co);
            }
        }
        cpa_commit();
    }

    for (int ch = 0; ch < 8; ch++) {
        if (ch < 7) cpa_wait1(); else cpa_wait0();
        __syncthreads();
        if (ch + 2 < 8) {
            u32 sb = base + (u32)(((ch + 2) % 3) * 32768);
            int co = (ch + 2) * 32;
#pragma unroll
            for (int i = 0; i < 4; i++) {
                if (st_xok[i]) {
                    cpa16(sb + st_bo[i], st_wsrc[i] + co);
                    cpa16(sb + 16384 + st_bo[i], st_xsrc[i] + co);
                } else if (need_lo) {
                    cpa16(sb + st_bo[i], st_wsrc[i] + co);
                }
            }
            cpa_commit();
        }
        u32 aU = base + (u32)((ch % 3) * 32768);
        u32 bU = aU + 16384u;
#pragma unroll
        for (int kkh = 0; kkh < 2; kkh++) {
            u32 kA = (u32)(kkh * 32);
            u32 ah[2][4];
            ldsm4(ah[0], aU + (a_off[0] ^ kA));
            ldsm4(ah[1], aU + (a_off[1] ^ kA));
            u32 bh[8][2];
#pragma unroll
            for (int j2 = 0; j2 < 4; j2++) {
                u32 r4[4];
                ldsm4(r4, bU + (b_off[j2] ^ kA));
                bh[2 * j2][0] = r4[0]; bh[2 * j2][1] = r4[1];
                bh[2 * j2 + 1][0] = r4[2]; bh[2 * j2 + 1][1] = r4[3];
            }
#pragma unroll
            for (int im = 0; im < 2; im++)
#pragma unroll
                for (int jn = 0; jn < 8; jn++)
                    mma16816(acc[im][jn], ah[im], bh[jn]);
            if (need_lo) {
                u32 al[2][4];
                ldsm4(al[0], aU + (a_off[0] ^ (kA + 64)));
                ldsm4(al[1], aU + (a_off[1] ^ (kA + 64)));
#pragma unroll
                for (int im = 0; im < 2; im++)
#pragma unroll
                    for (int jn = 0; jn < 8; jn++)
                        mma16816(acc[im][jn], al[im], bh[jn]);
            }
        }
    }

    // epilogue: q block -> f32 g_q; k/v blocks -> fp16 g_kv16
    int r0 = wm + (lane >> 2);
    int cb = wn + (lane & 3) * 2;
    if (mb == 0) {
#pragma unroll
        for (int im = 0; im < 2; im++) {
#pragma unroll
            for (int jn = 0; jn < 8; jn++) {
                int c = cb + jn * 8;
                size_t rowA = (size_t)b * PHID + r0 + im * 16;
                float2 v0 = {acc[im][jn][0], acc[im][jn][1]};
                float2 v1 = {acc[im][jn][2], acc[im][jn][3]};
                *reinterpret_cast<float2*>(&g_q[rowA * PN + nb + c]) = v0;
                *reinterpret_cast<float2*>(&g_q[(rowA + 8) * PN + nb + c]) = v1;
            }
        }
    } else {
        int kvbase = b * 256 + (mb - 128);   // k rows 0-127, v rows 128-255
#pragma unroll
        for (int im = 0; im < 2; im++) {
#pragma unroll
            for (int jn = 0; jn < 8; jn++) {
                int c = cb + jn * 8;
                size_t row = (size_t)(kvbase + r0 + im * 16);
                __half2 h0 = __floats2half2_rn(acc[im][jn][0], acc[im][jn][1]);
                __half2 h1 = __floats2half2_rn(acc[im][jn][2], acc[im][jn][3]);
                *reinterpret_cast<__half2*>(&g_kv16[row * PN + nb + c]) = h0;
                *reinterpret_cast<__half2*>(&g_kv16[(row + 8) * PN + nb + c]) = h1;
            }
        }
    }
}

// ---------------- K3a: k row softmax stats (fp16 k, uint4 loads) ----------------
__global__ void k_kstats(const float* __restrict__ mem_kv) {
    int gwarp = (blockIdx.x * blockDim.x + threadIdx.x) >> 5;
    int lane = threadIdx.x & 31;
    if (gwarp >= PB * PNH * PHD) return;
    int d = gwarp & 31, h = (gwarp >> 5) & 3, b = gwarp >> 7;
    const unsigned short* krow = &g_kv16[(size_t)(b * 256 + h * PHD + d) * PN];

    float m0 = -1e30f, m1 = -1e30f;
    for (int p = lane * 8; p < PN; p += 512) {
        uint4 va = *reinterpret_cast<const uint4*>(&krow[p]);
        uint4 vb = *reinterpret_cast<const uint4*>(&krow[p + 256]);
        const __half2* ha = reinterpret_cast<const __half2*>(&va);
        const __half2* hb = reinterpret_cast<const __half2*>(&vb);
#pragma unroll
        for (int j = 0; j < 4; j++) {
            float2 fa = __half22float2(ha[j]);
            float2 fb = __half22float2(hb[j]);
            m0 = fmaxf(m0, fmaxf(fa.x, fa.y));
            m1 = fmaxf(m1, fmaxf(fb.x, fb.y));
        }
    }
    float m = fmaxf(m0, m1);
    if (lane < PNM)
        m = fmaxf(m, mem_kv[((0 * PNH + h) * PHD + d) * PNM + lane]);
#pragma unroll
    for (int o = 16; o > 0; o >>= 1)
        m = fmaxf(m, __shfl_xor_sync(0xffffffffu, m, o));

    float s0 = 0.f, s1 = 0.f;
    for (int p = lane * 8; p < PN; p += 512) {
        uint4 va = *reinterpret_cast<const uint4*>(&krow[p]);
        uint4 vb = *reinterpret_cast<const uint4*>(&krow[p + 256]);
        const __half2* ha = reinterpret_cast<const __half2*>(&va);
        const __half2* hb = reinterpret_cast<const __half2*>(&vb);
#pragma unroll
        for (int j = 0; j < 4; j++) {
            float2 fa = __half22float2(ha[j]);
            float2 fb = __half22float2(hb[j]);
            s0 += __expf(fa.x - m) + __expf(fa.y - m);
            s1 += __expf(fb.x - m) + __expf(fb.y - m);
        }
    }
    float s = s0 + s1;
    if (lane < PNM)
        s += __expf(mem_kv[((0 * PNH + h) * PHD + d) * PNM + lane] - m);
#pragma unroll
    for (int o = 16; o > 0; o >>= 1)
        s += __shfl_xor_sync(0xffffffffu, s, o);
    if (lane == 0) { g_stat[0][gwarp] = m; g_stat[1][gwarp] = 1.0f / s; }
}

// ---------------- K3b: partial context (fp16 k/v loads) ----------------
__global__ void k_context(const float* __restrict__ mem_kv) {
    __shared__ float Ks[PHD][68];
    __shared__ float Vt[64][34];
    __shared__ float rmax[PHD], rinv[PHD];
    int tc = blockIdx.x, h = blockIdx.y, b = blockIdx.z;
    int tid = threadIdx.x;
    if (tid < PHD) {
        int rowid = (b * PNH + h) * PHD + tid;
        rmax[tid] = g_stat[0][rowid];
        rinv[tid] = g_stat[1][rowid];
    }
    __syncthreads();
    int d = tid >> 3;
    int eg = (tid & 7) << 2;
    float macc[4] = {0.f, 0.f, 0.f, 0.f};
    if (tc == 0) {
#pragma unroll
        for (int m = 0; m < PNM; m++) {
            float kv = __expf(mem_kv[((0 * PNH + h) * PHD + d) * PNM + m] - rmax[d]) * rinv[d];
#pragma unroll
            for (int i = 0; i < 4; i++)
                macc[i] += kv * mem_kv[((1 * PNH + h) * PHD + eg + i) * PNM + m];
        }
    }
    u64 accp[2] = {0ull, 0ull};
    int pbase = tc * 512;
    for (int t = 0; t < 8; t++) {
        int p0 = pbase + t * 64;
        {
            int r = tid >> 3, c8 = (tid & 7) << 3;
            uint4 v = *reinterpret_cast<const uint4*>(
                &g_kv16[(size_t)(b * 256 + h * PHD + r) * PN + p0 + c8]);
            const __half2* hp = reinterpret_cast<const __half2*>(&v);
            float mx = rmax[r], ri = rinv[r];
#pragma unroll
            for (int j = 0; j < 4; j++) {
                float2 f = __half22float2(hp[j]);
                Ks[r][c8 + 2 * j]     = __expf(f.x - mx) * ri;
                Ks[r][c8 + 2 * j + 1] = __expf(f.y - mx) * ri;
            }
        }
        {
            int r = tid >> 3, c8 = (tid & 7) << 3;
            uint4 v = *reinterpret_cast<const uint4*>(
                &g_kv16[(size_t)(b * 256 + 128 + h * PHD + r) * PN + p0 + c8]);
            const __half2* hp = reinterpret_cast<const __half2*>(&v);
#pragma unroll
            for (int j = 0; j < 4; j++) {
                float2 f = __half22float2(hp[j]);
                Vt[c8 + 2 * j][r] = f.x;
                Vt[c8 + 2 * j + 1][r] = f.y;
            }
        }
        __syncthreads();
#pragma unroll
        for (int n = 0; n < 64; n++) {
            u64 kv2 = pack2(Ks[d][n], Ks[d][n]);
            u64 v0 = *reinterpret_cast<const u64*>(&Vt[n][eg]);
            u64 v1 = *reinterpret_cast<const u64*>(&Vt[n][eg + 2]);
            accp[0] = fma2(kv2, v0, accp[0]);
            accp[1] = fma2(kv2, v1, accp[1]);
        }
        __syncthreads();
    }
    size_t base = ((size_t)(b * PNH + h) * PHD + d) * PHD + eg;
    float2 p0 = unpack2(accp[0]);
    float2 p1 = unpack2(accp[1]);
    g_ctxp[tc][base + 0] = p0.x + macc[0];
    g_ctxp[tc][base + 1] = p0.y + macc[1];
    g_ctxp[tc][base + 2] = p1.x + macc[2];
    g_ctxp[tc][base + 3] = p1.y + macc[3];
}

// ---------------- K4: reduce partials + fold M = w_out . ctx -> fp16 hi/lo ----------------
__global__ void k_fold(const float* __restrict__ w_out) {
    __shared__ float ctx[PNH * PHD * PHD];
    int b = blockIdx.x;
    int tid = threadIdx.x;
    for (int idx = tid; idx < PNH * PHD * PHD; idx += 256) {
        float s = 0.0f;
#pragma unroll
        for (int tc = 0; tc < 8; tc++) s += g_ctxp[tc][b * (PNH * PHD * PHD) + idx];
        ctx[idx] = s;
    }
    __syncthreads();
    int o = tid;
    for (int h = 0; h < PNH; h++) {
        float w[PHD];
#pragma unroll
        for (int e = 0; e < PHD; e++) w[e] = w_out[o * PHID + h * PHD + e];
        for (int dd = 0; dd < PHD; dd++) {
            float s = 0.0f;
#pragma unroll
            for (int e = 0; e < PHD; e++) s += w[e] * ctx[(h * PHD + dd) * PHD + e];
            u32 hb = f16_rn(s);
            u32 lb = f16_rn(s - f16_tof(hb));
            int idx = (b * PC + o) * PHID + h * PHD + dd;
            g_Mh[idx] = (unsigned short)hb;
            g_Ml[idx] = (unsigned short)lb;
        }
    }
}

// ---------------- K5: fused q-softmax + output GEMM (HMMA) + bias + RMS norm ----------------
#define OUT_SMEM 99584
__global__ void __launch_bounds__(256, 2) k_out_mma(
    const float* __restrict__ b_out,
    const float* __restrict__ g_out,
    float* __restrict__ out) {
    extern __shared__ char dyn[];
    u32 base = smem_u32(dyn);
    float* msf = reinterpret_cast<float*>(dyn + 32768);
    float* red = reinterpret_cast<float*>(dyn + 98304);
    float* invr = reinterpret_cast<float*>(dyn + 99328);
    int tid = threadIdx.x, lane = tid & 31, wid = tid >> 5;
    int p0 = blockIdx.x * 64, b = blockIdx.y;

#pragma unroll
    for (int i = 0; i < 8; i++) {
        int f4 = tid + i * 256;
        int r = f4 >> 4, c4 = (f4 & 15) << 2;
        *reinterpret_cast<float4*>(&msf[r * 64 + c4]) =
            *reinterpret_cast<const float4*>(&g_q[((size_t)b * PHID + r) * PN + p0 + c4]);
    }
    __syncthreads();

    {
        int p = tid & 63, h = tid >> 6;
        float e[PHD];
        float m = -1e30f;
#pragma unroll
        for (int dd = 0; dd < PHD; dd++) m = fmaxf(m, msf[(h * PHD + dd) * 64 + p]);
        float s = 0.0f;
#pragma unroll
        for (int dd = 0; dd < PHD; dd++) { e[dd] = __expf(msf[(h * PHD + dd) * 64 + p] - m); s += e[dd]; }
        float sc = 0.17677669529663687f / s;
        int kc = h >> 1;
        int klb = (h & 1) * 32;
        u32 qh_off = (u32)(kc * 8192);
        __syncthreads();
#pragma unroll
        for (int dd = 0; dd < PHD; dd += 2) {
            float v0 = e[dd] * sc, v1 = e[dd + 1] * sc;
            u32 h0 = f16_rn(v0), h1 = f16_rn(v1);
            u32 bo = (u32)(p * 128 + (klb + dd) * 2);
            bo ^= (bo >> 3) & 0x70;
            *reinterpret_cast<u32*>(dyn + qh_off + bo) = (h1 << 16) | h0;
        }
    }
    __syncthreads();

    int wm = wid & 3, wn = wid >> 2;
    float acc[4][4][4];
#pragma unroll
    for (int im = 0; im < 4; im++)
#pragma unroll
        for (int jn = 0; jn < 4; jn++)
#pragma unroll
            for (int q = 0; q < 4; q++) acc[im][jn][q] = 0.0f;

    u32 a_off[4], b_off[2];
#pragma unroll
    for (int im = 0; im < 4; im++) {
        int arow = wm * 64 + im * 16 + (lane & 15);
        u32 bo = (u32)(arow * 128) + ((lane >> 4) << 4);
        a_off[im] = bo ^ ((bo >> 3) & 0x70);
    }
#pragma unroll
    for (int j2 = 0; j2 < 2; j2++) {
        int nrow = wn * 32 + j2 * 16 + ((lane >> 4) << 3) + (lane & 7);
        u32 bo = (u32)(nrow * 128) + (((lane >> 3) & 1) << 4);
        b_off[j2] = bo ^ ((bo >> 3) & 0x70);
    }
    u32 mh_base = base + 32768u, ml_base = base + 65536u;

    for (int kc = 0; kc < 2; kc++) {
        u32 qh = base + (u32)(kc * 8192);
#pragma unroll
        for (int i = 0; i < 8; i++) {
            int u = tid + i * 256;
            int r = u >> 3, c8 = (u & 7) << 3;
            u32 bo = (u32)((r << 7) + (c8 << 1));
            bo ^= (bo >> 3) & 0x70;
            int gi = (b * PC + r) * PHID + kc * 64 + c8;
            *reinterpret_cast<uint4*>(dyn + 32768 + bo) =
                *reinterpret_cast<const uint4*>(&g_Mh[gi]);
            *reinterpret_cast<uint4*>(dyn + 65536 + bo) =
                *reinterpret_cast<const uint4*>(&g_Ml[gi]);
        }
        __syncthreads();
#pragma unroll
        for (int kk = 0; kk < 4; kk++) {
            u32 kadd = (u32)(kk * 32);
            u32 a[4][4];
#pragma unroll
            for (int im = 0; im < 4; im++) ldsm4(a[im], mh_base + (a_off[im] ^ kadd));
            u32 al[4][4];
#pragma unroll
            for (int im = 0; im < 4; im++) ldsm4(al[im], ml_base + (a_off[im] ^ kadd));
            u32 bh[4][2];
#pragma unroll
            for (int j2 = 0; j2 < 2; j2++) {
                u32 r4[4];
                ldsm4(r4, qh + (b_off[j2] ^ kadd));
                bh[2 * j2][0] = r4[0]; bh[2 * j2][1] = r4[1];
                bh[2 * j2 + 1][0] = r4[2]; bh[2 * j2 + 1][1] = r4[3];
            }
#pragma unroll
            for (int im = 0; im < 4; im++)
#pragma unroll
                for (int jn = 0; jn < 4; jn++)
                    mma16816(acc[im][jn], a[im], bh[jn]);
#pragma unroll
            for (int im = 0; im < 4; im++)
#pragma unroll
                for (int jn = 0; jn < 4; jn++)
                    mma16816(acc[im][jn], al[im], bh[jn]);
        }
        __syncthreads();
    }

    float bo0[4], bo8[4], go0[4], go8[4];
#pragma unroll
    for (int im = 0; im < 4; im++) {
        int r = wm * 64 + im * 16 + (lane >> 2);
        bo0[im] = b_out[r];  bo8[im] = b_out[r + 8];
        go0[im] = g_out[r];  go8[im] = g_out[r + 8];
    }
#pragma unroll
    for (int jn = 0; jn < 4; jn++) {
        float sq0 = 0.f, sq1 = 0.f;
#pragma unroll
        for (int im = 0; im < 4; im++) {
            acc[im][jn][0] += bo0[im]; acc[im][jn][1] += bo0[im];
            acc[im][jn][2] += bo8[im]; acc[im][jn][3] += bo8[im];
            sq0 += acc[im][jn][0] * acc[im][jn][0] + acc[im][jn][2] * acc[im][jn][2];
            sq1 += acc[im][jn][1] * acc[im][jn][1] + acc[im][jn][3] * acc[im][jn][3];
        }
#pragma unroll
        for (int off = 4; off < 32; off <<= 1) {
            sq0 += __shfl_xor_sync(0xffffffffu, sq0, off);
            sq1 += __shfl_xor_sync(0xffffffffu, sq1, off);
        }
        if (lane < 4) {
            int c = wn * 32 + jn * 8 + lane * 2;
            red[wm * 64 + c] = sq0;
            red[wm * 64 + c + 1] = sq1;
        }
    }
    __syncthreads();
    if (tid < 64) {
        float s = red[tid] + red[64 + tid] + red[128 + tid] + red[192 + tid];
        invr[tid] = 16.0f / fmaxf(sqrtf(s), 1e-12f);
    }
    __syncthreads();
#pragma unroll
    for (int im = 0; im < 4; im++) {
        int r = wm * 64 + im * 16 + (lane >> 2);
#pragma unroll
        for (int jn = 0; jn < 4; jn++) {
            int c = wn * 32 + jn * 8 + (lane & 3) * 2;
            float iv0 = invr[c], iv1 = invr[c + 1];
            float2 v0 = {acc[im][jn][0] * iv0 * go0[im], acc[im][jn][1] * iv1 * go0[im]};
            float2 v1 = {acc[im][jn][2] * iv0 * go8[im], acc[im][jn][3] * iv1 * go8[im]};
            *reinterpret_cast<float2*>(&out[((size_t)(b * PC + r)) * PN + p0 + c]) = v0;
            *reinterpret_cast<float2*>(&out[((size_t)(b * PC + r + 8)) * PN + p0 + c]) = v1;
        }
    }
}

// ---------------- launch: fork/join stream overlap ----------------
// stream0: convw, normx, qkv(kv), qkv(q) ............ join ... k_out
// stream2:                      \-> kstats, context, fold -/
extern "C" void kernel_launch(void* const* d_in, const int* in_sizes, int n_in,
                              void* d_out, int out_size) {
    const float* x      = (const float*)d_in[0];
    const float* g_in   = (const float*)d_in[1];
    const float* mem_kv = (const float*)d_in[2];
    const float* w_qkv  = (const float*)d_in[3];
    const float* w_out  = (const float*)d_in[4];
    const float* b_out  = (const float*)d_in[5];
    const float* g_out  = (const float*)d_in[6];
    float* out = (float*)d_out;

    static cudaStream_t s2 = 0;
    static cudaEvent_t ev_kv = 0, ev_chain = 0;
    static int init_done = 0;
    if (!init_done) {
        cudaFuncSetAttribute(k_normx,   cudaFuncAttributeMaxDynamicSharedMemorySize, NORMX_SMEM);
        cudaFuncSetAttribute(k_qkv_mma, cudaFuncAttributeMaxDynamicSharedMemorySize, QKV_SMEM);
        cudaFuncSetAttribute(k_out_mma, cudaFuncAttributeMaxDynamicSharedMemorySize, OUT_SMEM);
        cudaStreamCreateWithFlags(&s2, cudaStreamNonBlocking);
        cudaEventCreateWithFlags(&ev_kv, cudaEventDisableTiming);
        cudaEventCreateWithFlags(&ev_chain, cudaEventDisableTiming);
        init_done = 1;
    }

    k_convw  <<<QROWS, 256>>>(w_qkv, g_in);
    k_normx  <<<dim3(PN / 64, PB), 256, NORMX_SMEM>>>(x);
    // k/v blocks first; q block overlaps with the stats/context/fold chain
    k_qkv_mma<<<dim3(PN / 128, 2, PB), 256, QKV_SMEM>>>(128);
    cudaEventRecord(ev_kv, 0);
    k_qkv_mma<<<dim3(PN / 128, 1, PB), 256, QKV_SMEM>>>(0);

    cudaStreamWaitEvent(s2, ev_kv, 0);
    k_kstats <<<512, 128, 0, s2>>>(mem_kv);
    k_context<<<dim3(8, PNH, PB), 256, 0, s2>>>(mem_kv);
    k_fold   <<<PB, 256, 0, s2>>>(w_out);
    cudaEventRecord(ev_chain, s2);

    cudaStreamWaitEvent(0, ev_chain, 0);
    k_out_mma<<<dim3(PN / 64, PB), 256, OUT_SMEM>>>(b_out, g_out, out);
}